// round 1
// baseline (speedup 1.0000x reference)
#include <cuda_runtime.h>
#include <cstdint>

// Stacked LSTM (2 layers, D=H=6) + softmax.
// Mapping: one lane per (batch element, hidden unit j). Lane holds weight rows
// {j, j+6, j+12, j+18} (gates i,f,g,o for unit j) of both layers in registers.
// 5 elements per warp (lanes 0..29), groups of 6 lanes; h broadcast via shfl.
// Layers are software-pipelined with a 1-step skew for ILP:
//   iteration t computes layer0(t) and layer1(t-1) (independent chains).

#define FULLMASK 0xFFFFFFFFu

__device__ __forceinline__ float ex2f(float x) {
    float r; asm("ex2.approx.f32 %0, %1;" : "=f"(r) : "f"(x)); return r;
}
__device__ __forceinline__ float rcpf(float x) {
    float r; asm("rcp.approx.f32 %0, %1;" : "=f"(r) : "f"(x)); return r;
}
// sigmoid(x) = 1 / (1 + exp(-x)) = 1 / (1 + 2^(-x*log2e))
__device__ __forceinline__ float sigf(float x) {
    return rcpf(1.0f + ex2f(-1.4426950408889634f * x));
}
// tanh(x) = 2/(1+exp(-2x)) - 1
__device__ __forceinline__ float tanh_(float x) {
    return fmaf(2.0f, rcpf(1.0f + ex2f(-2.8853900817779268f * x)), -1.0f);
}

__device__ __forceinline__ void cell(const float wi[4][6], const float wh[4][6],
                                     const float bz[4],
                                     const float in[6], const float hb[6],
                                     float& c, float& nh) {
    float a0 = bz[0], a1 = bz[1], a2 = bz[2], a3 = bz[3];
#pragma unroll
    for (int d = 0; d < 6; ++d) {
        a0 = fmaf(wi[0][d], in[d], a0);
        a1 = fmaf(wi[1][d], in[d], a1);
        a2 = fmaf(wi[2][d], in[d], a2);
        a3 = fmaf(wi[3][d], in[d], a3);
    }
#pragma unroll
    for (int d = 0; d < 6; ++d) {
        a0 = fmaf(wh[0][d], hb[d], a0);
        a1 = fmaf(wh[1][d], hb[d], a1);
        a2 = fmaf(wh[2][d], hb[d], a2);
        a3 = fmaf(wh[3][d], hb[d], a3);
    }
    float ig = sigf(a0);
    float fg = sigf(a1);
    float gg = tanh_(a2);
    float og = sigf(a3);
    c  = fmaf(fg, c, ig * gg);
    nh = og * tanh_(c);
}

__global__ __launch_bounds__(128, 1)
void stacked_lstm_kernel(const float* __restrict__ x,
                         const float* __restrict__ Wih0, const float* __restrict__ Whh0,
                         const float* __restrict__ bih0, const float* __restrict__ bhh0,
                         const float* __restrict__ Wih1, const float* __restrict__ Whh1,
                         const float* __restrict__ bih1, const float* __restrict__ bhh1,
                         float* __restrict__ out,
                         int B, int T) {
    const int lane = threadIdx.x & 31;
    const int warp_global = (blockIdx.x * blockDim.x + threadIdx.x) >> 5;
    const int g = lane / 6;          // group within warp (0..4 active, 5 = idle lanes 30,31)
    const int j = lane - g * 6;      // hidden unit owned by this lane
    const int base = g * 6;          // first lane of this group (for shfl)
    const int b = warp_global * 5 + g;
    const bool valid = (g < 5) && (b < B);
    const int bc = (b < B) ? b : (B - 1);   // clamped for safe loads on idle lanes

    // ---- load this lane's weight rows into registers ----
    float wi0r[4][6], wh0r[4][6], bz0[4];
    float wi1r[4][6], wh1r[4][6], bz1[4];
#pragma unroll
    for (int q = 0; q < 4; ++q) {
        int r = q * 6 + j;
        bz0[q] = bih0[r] + bhh0[r];
        bz1[q] = bih1[r] + bhh1[r];
#pragma unroll
        for (int d = 0; d < 6; ++d) {
            wi0r[q][d] = Wih0[r * 6 + d];
            wh0r[q][d] = Whh0[r * 6 + d];
            wi1r[q][d] = Wih1[r * 6 + d];
            wh1r[q][d] = Whh1[r * 6 + d];
        }
    }

    // ---- state ----
    float c0 = 0.0f, c1 = 0.0f;
    float h0b[6], h1b[6];
#pragma unroll
    for (int k = 0; k < 6; ++k) { h0b[k] = 0.0f; h1b[k] = 0.0f; }

    // x row for this element: 6 floats per step, 8B aligned -> 3x float2
    const float2* xp = reinterpret_cast<const float2*>(x + (size_t)bc * (size_t)T * 6);
    float2 cx0 = xp[0], cx1 = xp[1], cx2 = xp[2];

    float nh0, nh1;

    // ---- t = 0: layer0 only (layer1 skewed by one step) ----
    {
        float xin[6] = {cx0.x, cx0.y, cx1.x, cx1.y, cx2.x, cx2.y};
        // prefetch t=1
        cx0 = xp[3]; cx1 = xp[4]; cx2 = xp[5];
        asm volatile("prefetch.global.L2 [%0];" :: "l"(xp + 3 * 32));
        cell(wi0r, wh0r, bz0, xin, h0b, c0, nh0);
#pragma unroll
        for (int k = 0; k < 6; ++k) h0b[k] = __shfl_sync(FULLMASK, nh0, base + k);
    }

    // ---- main loop: iteration t does layer0(t) and layer1(t-1) ----
    for (int t = 1; t < T; ++t) {
        float xin[6] = {cx0.x, cx0.y, cx1.x, cx1.y, cx2.x, cx2.y};
        int tn = (t + 1 < T) ? (t + 1) : t;
        cx0 = xp[3 * tn];
        cx1 = xp[3 * tn + 1];
        cx2 = xp[3 * tn + 2];
        if (t + 32 < T)
            asm volatile("prefetch.global.L2 [%0];" :: "l"(xp + 3 * (t + 32)));

        // two independent chains -> ILP
        cell(wi0r, wh0r, bz0, xin, h0b, c0, nh0);   // layer0 @ t   (reads h0b = h0(t-1))
        cell(wi1r, wh1r, bz1, h0b, h1b, c1, nh1);   // layer1 @ t-1 (reads h0(t-1), h1(t-2))

#pragma unroll
        for (int k = 0; k < 6; ++k) h0b[k] = __shfl_sync(FULLMASK, nh0, base + k);
#pragma unroll
        for (int k = 0; k < 6; ++k) h1b[k] = __shfl_sync(FULLMASK, nh1, base + k);
    }

    // ---- final skewed layer1 step @ t = T-1 ----
    cell(wi1r, wh1r, bz1, h0b, h1b, c1, nh1);
#pragma unroll
    for (int k = 0; k < 6; ++k) h1b[k] = __shfl_sync(FULLMASK, nh1, base + k);

    // ---- softmax over the 6 units; lane j writes out[b, j] ----
    if (valid) {
        float m = h1b[0];
#pragma unroll
        for (int k = 1; k < 6; ++k) m = fmaxf(m, h1b[k]);
        float s = 0.0f;
#pragma unroll
        for (int k = 0; k < 6; ++k) s += ex2f(1.4426950408889634f * (h1b[k] - m));
        float e = ex2f(1.4426950408889634f * (h1b[j] - m));
        out[b * 6 + j] = e * rcpf(s);
    }
}

extern "C" void kernel_launch(void* const* d_in, const int* in_sizes, int n_in,
                              void* d_out, int out_size) {
    const float* x    = (const float*)d_in[0];
    const float* Wih0 = (const float*)d_in[1];
    const float* Whh0 = (const float*)d_in[2];
    const float* bih0 = (const float*)d_in[3];
    const float* bhh0 = (const float*)d_in[4];
    const float* Wih1 = (const float*)d_in[5];
    const float* Whh1 = (const float*)d_in[6];
    const float* bih1 = (const float*)d_in[7];
    const float* bhh1 = (const float*)d_in[8];
    float* out = (float*)d_out;

    int B = out_size / 6;                               // 2048
    int T = (int)((long long)in_sizes[0] / ((long long)B * 6));  // 2048

    int warps = (B + 4) / 5;          // 5 elements per warp
    int blocks = (warps + 3) / 4;     // 4 warps per block (128 threads)
    stacked_lstm_kernel<<<blocks, 128>>>(x, Wih0, Whh0, bih0, bhh0,
                                         Wih1, Whh1, bih1, bhh1, out, B, T);
}

// round 3
// speedup vs baseline: 1.3800x; 1.3800x over previous
#include <cuda_runtime.h>
#include <cstdint>

// Stacked LSTM (2 layers, D=H=6) + softmax, latency-optimized for sm_103a.
// One lane per (batch element, hidden unit j); weight rows in registers;
// h broadcast via shfl; layers software-pipelined with 1-step skew.
// Nonlinearities via hardware tanh.approx.f32:
//   tanh(x)    = 1 MUFU
//   sigmoid(x) = 0.5*tanh(x/2)+0.5, with the /2 folded into pre-halved
//                weight rows for gates i,f,o -> TANH + FFMA only.

#define FULLMASK 0xFFFFFFFFu

__device__ __forceinline__ float ex2f(float x) {
    float r; asm("ex2.approx.f32 %0, %1;" : "=f"(r) : "f"(x)); return r;
}
__device__ __forceinline__ float rcpf(float x) {
    float r; asm("rcp.approx.f32 %0, %1;" : "=f"(r) : "f"(x)); return r;
}
__device__ __forceinline__ float htanh(float x) {
    float r; asm("tanh.approx.f32 %0, %1;" : "=f"(r) : "f"(x)); return r;
}

// Gate rows for i,f,o are PRE-HALVED (weights+bias), g is full scale.
__device__ __forceinline__ void cell(const float wi[4][6], const float wh[4][6],
                                     const float bz[4],
                                     const float in[6], const float hb[6],
                                     float& c, float& nh) {
    float a0 = bz[0], a1 = bz[1], a2 = bz[2], a3 = bz[3];
#pragma unroll
    for (int d = 0; d < 6; ++d) {
        a0 = fmaf(wi[0][d], in[d], a0);
        a1 = fmaf(wi[1][d], in[d], a1);
        a2 = fmaf(wi[2][d], in[d], a2);
        a3 = fmaf(wi[3][d], in[d], a3);
    }
#pragma unroll
    for (int d = 0; d < 6; ++d) {
        a0 = fmaf(wh[0][d], hb[d], a0);
        a1 = fmaf(wh[1][d], hb[d], a1);
        a2 = fmaf(wh[2][d], hb[d], a2);
        a3 = fmaf(wh[3][d], hb[d], a3);
    }
    float ig = fmaf(0.5f, htanh(a0), 0.5f);   // sigmoid via tanh
    float fg = fmaf(0.5f, htanh(a1), 0.5f);
    float gg = htanh(a2);
    float og = fmaf(0.5f, htanh(a3), 0.5f);
    c  = fmaf(fg, c, ig * gg);
    nh = og * htanh(c);
}

__global__ __launch_bounds__(128, 1)
void stacked_lstm_kernel(const float* __restrict__ x,
                         const float* __restrict__ Wih0, const float* __restrict__ Whh0,
                         const float* __restrict__ bih0, const float* __restrict__ bhh0,
                         const float* __restrict__ Wih1, const float* __restrict__ Whh1,
                         const float* __restrict__ bih1, const float* __restrict__ bhh1,
                         float* __restrict__ out,
                         int B, int T) {
    const int lane = threadIdx.x & 31;
    const int warp_global = (blockIdx.x * blockDim.x + threadIdx.x) >> 5;
    const int g = lane / 6;          // group within warp (0..4 active)
    const int j = lane - g * 6;      // hidden unit owned by this lane
    const int base = g * 6;          // first lane of group (for shfl)
    const int b = warp_global * 5 + g;
    const bool valid = (g < 5) && (b < B);
    const int bc = (b < B) ? b : (B - 1);

    // ---- weights into registers; i,f,o rows pre-halved for sigmoid-via-tanh ----
    float wi0r[4][6], wh0r[4][6], bz0[4];
    float wi1r[4][6], wh1r[4][6], bz1[4];
#pragma unroll
    for (int q = 0; q < 4; ++q) {
        const float s = (q == 2) ? 1.0f : 0.5f;   // gate order i,f,g,o
        int r = q * 6 + j;
        bz0[q] = (bih0[r] + bhh0[r]) * s;
        bz1[q] = (bih1[r] + bhh1[r]) * s;
#pragma unroll
        for (int d = 0; d < 6; ++d) {
            wi0r[q][d] = Wih0[r * 6 + d] * s;
            wh0r[q][d] = Whh0[r * 6 + d] * s;
            wi1r[q][d] = Wih1[r * 6 + d] * s;
            wh1r[q][d] = Whh1[r * 6 + d] * s;
        }
    }

    // ---- state ----
    float c0 = 0.0f, c1 = 0.0f;
    float h0b[6], h1b[6];
#pragma unroll
    for (int k = 0; k < 6; ++k) { h0b[k] = 0.0f; h1b[k] = 0.0f; }

    const float2* xp = reinterpret_cast<const float2*>(x + (size_t)bc * (size_t)T * 6);
    float2 cx0 = xp[0], cx1 = xp[1], cx2 = xp[2];

    float nh0, nh1;

    // ---- t = 0: layer0 only ----
    {
        float xin[6] = {cx0.x, cx0.y, cx1.x, cx1.y, cx2.x, cx2.y};
        cx0 = xp[3]; cx1 = xp[4]; cx2 = xp[5];
        asm volatile("prefetch.global.L2 [%0];" :: "l"(xp + 3 * 32));
        cell(wi0r, wh0r, bz0, xin, h0b, c0, nh0);
#pragma unroll
        for (int k = 0; k < 6; ++k) h0b[k] = __shfl_sync(FULLMASK, nh0, base + k);
    }

    // ---- main: iteration t = layer0(t) + layer1(t-1), double-buffered h ----
#pragma unroll 2
    for (int t = 1; t < T; ++t) {
        float xin[6] = {cx0.x, cx0.y, cx1.x, cx1.y, cx2.x, cx2.y};
        int tn = (t + 1 < T) ? (t + 1) : t;
        cx0 = xp[3 * tn];
        cx1 = xp[3 * tn + 1];
        cx2 = xp[3 * tn + 2];
        if (t + 32 < T)
            asm volatile("prefetch.global.L2 [%0];" :: "l"(xp + 3 * (t + 32)));

        // layer0 @ t (reads h0b = h0(t-1))
        cell(wi0r, wh0r, bz0, xin, h0b, c0, nh0);

        // start h0 broadcast into a fresh buffer; overlaps layer1 compute
        float h0n[6];
#pragma unroll
        for (int k = 0; k < 6; ++k) h0n[k] = __shfl_sync(FULLMASK, nh0, base + k);

        // layer1 @ t-1 (reads old h0b, h1b)
        cell(wi1r, wh1r, bz1, h0b, h1b, c1, nh1);
#pragma unroll
        for (int k = 0; k < 6; ++k) h1b[k] = __shfl_sync(FULLMASK, nh1, base + k);

#pragma unroll
        for (int k = 0; k < 6; ++k) h0b[k] = h0n[k];
    }

    // ---- final skewed layer1 step @ t = T-1 ----
    cell(wi1r, wh1r, bz1, h0b, h1b, c1, nh1);
#pragma unroll
    for (int k = 0; k < 6; ++k) h1b[k] = __shfl_sync(FULLMASK, nh1, base + k);

    // ---- softmax over 6 units; lane j writes out[b, j] ----
    if (valid) {
        float m = h1b[0];
#pragma unroll
        for (int k = 1; k < 6; ++k) m = fmaxf(m, h1b[k]);
        float s = 0.0f;
#pragma unroll
        for (int k = 0; k < 6; ++k) s += ex2f(1.4426950408889634f * (h1b[k] - m));
        float e = ex2f(1.4426950408889634f * (h1b[j] - m));
        out[b * 6 + j] = e * rcpf(s);
    }
}

extern "C" void kernel_launch(void* const* d_in, const int* in_sizes, int n_in,
                              void* d_out, int out_size) {
    const float* x    = (const float*)d_in[0];
    const float* Wih0 = (const float*)d_in[1];
    const float* Whh0 = (const float*)d_in[2];
    const float* bih0 = (const float*)d_in[3];
    const float* bhh0 = (const float*)d_in[4];
    const float* Wih1 = (const float*)d_in[5];
    const float* Whh1 = (const float*)d_in[6];
    const float* bih1 = (const float*)d_in[7];
    const float* bhh1 = (const float*)d_in[8];
    float* out = (float*)d_out;

    int B = out_size / 6;
    int T = (int)((long long)in_sizes[0] / ((long long)B * 6));

    int warps = (B + 4) / 5;
    int blocks = (warps + 3) / 4;
    stacked_lstm_kernel<<<blocks, 128>>>(x, Wih0, Whh0, bih0, bhh0,
                                         Wih1, Whh1, bih1, bhh1, out, B, T);
}